// round 2
// baseline (speedup 1.0000x reference)
#include <cuda_runtime.h>
#include <cuda_bf16.h>
#include <cstdint>

// Problem shapes (fixed by the dataset)
static constexpr int Bb = 8;     // batch
static constexpr int Nn = 1024;  // tokens
static constexpr int Dd = 512;   // feature dim
static constexpr int Hh = 4;     // heads
static constexpr float SCALE = 0.04419417382415922f; // 512^-0.5

// Scratch (allocation-free rule -> __device__ globals)
__device__ float g_Y[(size_t)Bb * Hh * Nn * Dd];   // 64 MB  : x @ W per (b,h)
__device__ float g_L[(size_t)Bb * Hh * Nn * Nn];   // 128 MB : logits per (b,h)
__device__ float g_P[(size_t)Bb * Nn * Nn];        // 32 MB  : head-averaged softmax

// ---------------------------------------------------------------------------
// Generic fp32 SGEMM tile body: C = alpha * A * op(B)
//   A: [M,K] row-major.  TRANSB=false: B [K,N] row-major.  TRANSB=true: B [N,K] row-major.
//   BM=BN=128, BK=8, 256 threads, 8x8 per thread. M,N multiples of 128; K multiple of 8.
// ---------------------------------------------------------------------------
template <bool TRANSB>
__device__ __forceinline__ void sgemm_body(
    const float* __restrict__ A, const float* __restrict__ B,
    float* __restrict__ C, int M, int N, int K, float alpha)
{
    __shared__ float As[8][128];
    __shared__ float Bs[8][128];

    const int tid   = threadIdx.x;
    const int mBase = blockIdx.y * 128;
    const int nBase = blockIdx.x * 128;
    const int ty    = tid >> 4;   // 0..15
    const int tx    = tid & 15;   // 0..15

    float acc[8][8];
#pragma unroll
    for (int i = 0; i < 8; i++)
#pragma unroll
        for (int j = 0; j < 8; j++) acc[i][j] = 0.0f;

    const int arow = tid >> 1;         // 0..127
    const int ak   = (tid & 1) * 4;    // 0 or 4
    const int brow = tid >> 5;         // 0..7   (non-trans path)
    const int bc   = (tid & 31) * 4;   // 0..124 (non-trans path)

    for (int k0 = 0; k0 < K; k0 += 8) {
        // load A tile (transpose into smem)
        float4 av = *(const float4*)(A + (size_t)(mBase + arow) * K + k0 + ak);
        As[ak + 0][arow] = av.x;
        As[ak + 1][arow] = av.y;
        As[ak + 2][arow] = av.z;
        As[ak + 3][arow] = av.w;
        // load B tile
        if (TRANSB) {
            float4 bv = *(const float4*)(B + (size_t)(nBase + arow) * K + k0 + ak);
            Bs[ak + 0][arow] = bv.x;
            Bs[ak + 1][arow] = bv.y;
            Bs[ak + 2][arow] = bv.z;
            Bs[ak + 3][arow] = bv.w;
        } else {
            float4 bv = *(const float4*)(B + (size_t)(k0 + brow) * N + nBase + bc);
            *(float4*)&Bs[brow][bc] = bv;
        }
        __syncthreads();

#pragma unroll
        for (int k = 0; k < 8; k++) {
            float ar[8], br[8];
            *(float4*)&ar[0] = *(const float4*)&As[k][ty * 8];
            *(float4*)&ar[4] = *(const float4*)&As[k][ty * 8 + 4];
            *(float4*)&br[0] = *(const float4*)&Bs[k][tx * 8];
            *(float4*)&br[4] = *(const float4*)&Bs[k][tx * 8 + 4];
#pragma unroll
            for (int i = 0; i < 8; i++)
#pragma unroll
                for (int j = 0; j < 8; j++)
                    acc[i][j] = fmaf(ar[i], br[j], acc[i][j]);
        }
        __syncthreads();
    }

    // epilogue
#pragma unroll
    for (int i = 0; i < 8; i++) {
        float* crow = C + (size_t)(mBase + ty * 8 + i) * N + nBase + tx * 8;
        float4 o0, o1;
        o0.x = alpha * acc[i][0]; o0.y = alpha * acc[i][1];
        o0.z = alpha * acc[i][2]; o0.w = alpha * acc[i][3];
        o1.x = alpha * acc[i][4]; o1.y = alpha * acc[i][5];
        o1.z = alpha * acc[i][6]; o1.w = alpha * acc[i][7];
        *(float4*)(crow)     = o0;
        *(float4*)(crow + 4) = o1;
    }
}

// ---------------------------------------------------------------------------
// Kernel 1: Y[b,h] = x_b @ W_h         grid(4, 8, 32)
// ---------------------------------------------------------------------------
__global__ void __launch_bounds__(256) k1_xw(const float* __restrict__ x,
                                             const float* __restrict__ W)
{
    const int batch = blockIdx.z;        // b*4 + h
    const int b = batch >> 2, h = batch & 3;
    sgemm_body<false>(x + (size_t)b * Nn * Dd,
                      W + (size_t)h * Dd * Dd,
                      g_Y + (size_t)batch * Nn * Dd,
                      Nn, Dd, Dd, 1.0f);
}

// ---------------------------------------------------------------------------
// Kernel 2: L[b,h] = (Y[b,h] @ x_b^T) * scale     grid(8, 8, 32)
// ---------------------------------------------------------------------------
__global__ void __launch_bounds__(256) k2_logits(const float* __restrict__ x)
{
    const int batch = blockIdx.z;
    const int b = batch >> 2;
    sgemm_body<true>(g_Y + (size_t)batch * Nn * Dd,
                     x + (size_t)b * Nn * Dd,
                     g_L + (size_t)batch * Nn * Nn,
                     Nn, Nn, Dd, SCALE);
}

// ---------------------------------------------------------------------------
// Kernel 3: Pavg[b,n,:] = (1/H) * sum_h softmax(L[b,h,n,:])   grid(1024, 8)
// Pure-FMA exp (avoids the MUFU.EX2 throughput wall: rt_SMSP=8 would cost ~1ms
// for 134M exps).
// ---------------------------------------------------------------------------
__device__ __forceinline__ float fexp(float xv)
{
    // exp(x) = 2^(x*log2e); deg-6 Taylor of 2^f on [0,1), rel err ~1.5e-5
    float t  = fmaxf(xv * 1.44269504088896341f, -125.0f);
    float fi = floorf(t);
    float f  = t - fi;
    const float c1 = 0.69314718055994531f, c2 = 0.24022650695910072f,
                c3 = 0.05550410866482158f, c4 = 0.00961812910762848f,
                c5 = 0.00133335581464284f, c6 = 0.00015403530393382f;
    float p = fmaf(c6, f, c5);
    p = fmaf(p, f, c4);
    p = fmaf(p, f, c3);
    p = fmaf(p, f, c2);
    p = fmaf(p, f, c1);
    p = fmaf(p, f, 1.0f);
    int i = (int)fi;                       // -125..0
    return p * __int_as_float((i + 127) << 23);
}

template <bool IS_MAX>
__device__ __forceinline__ float breduce(float v, float* red)
{
    const int lane = threadIdx.x & 31, warp = threadIdx.x >> 5;
#pragma unroll
    for (int o = 16; o; o >>= 1) {
        float t = __shfl_xor_sync(0xffffffffu, v, o);
        v = IS_MAX ? fmaxf(v, t) : (v + t);
    }
    if (lane == 0) red[warp] = v;
    __syncthreads();
    if (warp == 0) {
        float t2 = red[lane & 7];
#pragma unroll
        for (int o = 4; o; o >>= 1) {
            float t = __shfl_xor_sync(0xffffffffu, t2, o);
            t2 = IS_MAX ? fmaxf(t2, t) : (t2 + t);
        }
        if (lane == 0) red[0] = t2;
    }
    __syncthreads();
    float r = red[0];
    __syncthreads();   // red[] is reused by the caller
    return r;
}

__global__ void __launch_bounds__(256) k3_softmax_avg()
{
    __shared__ float red[8];
    const int n = blockIdx.x;
    const int b = blockIdx.y;
    const int tid = threadIdx.x;

    float acc0 = 0.f, acc1 = 0.f, acc2 = 0.f, acc3 = 0.f;
#pragma unroll
    for (int h = 0; h < Hh; h++) {
        const float* row = g_L + (((size_t)(b * Hh + h)) * Nn + n) * Nn;
        float4 v = *(const float4*)(row + tid * 4);
        float m = fmaxf(fmaxf(v.x, v.y), fmaxf(v.z, v.w));
        m = breduce<true>(m, red);
        float e0 = fexp(v.x - m), e1 = fexp(v.y - m);
        float e2 = fexp(v.z - m), e3 = fexp(v.w - m);
        float s = breduce<false>(e0 + e1 + e2 + e3, red);
        float inv = 0.25f / s;               // fold 1/H into the softmax
        acc0 = fmaf(e0, inv, acc0);
        acc1 = fmaf(e1, inv, acc1);
        acc2 = fmaf(e2, inv, acc2);
        acc3 = fmaf(e3, inv, acc3);
    }
    float4 o = make_float4(acc0, acc1, acc2, acc3);
    *(float4*)(g_P + ((size_t)(b * Nn + n)) * Nn + tid * 4) = o;
}

// ---------------------------------------------------------------------------
// Kernel 4: out[b] = Pavg[b] @ x_b     grid(4, 8, 8)
// ---------------------------------------------------------------------------
__global__ void __launch_bounds__(256) k4_out(const float* __restrict__ x,
                                              float* __restrict__ out)
{
    const int b = blockIdx.z;
    sgemm_body<false>(g_P + (size_t)b * Nn * Nn,
                      x + (size_t)b * Nn * Dd,
                      out + (size_t)b * Nn * Dd,
                      Nn, Dd, Nn, 1.0f);
}

// ---------------------------------------------------------------------------
extern "C" void kernel_launch(void* const* d_in, const int* in_sizes, int n_in,
                              void* d_out, int out_size)
{
    const float* x = (const float*)d_in[0];   // [8,1024,512]
    const float* W = (const float*)d_in[1];   // [4,512,512]
    float* out = (float*)d_out;               // [8,1024,512]

    dim3 blk(256);
    k1_xw<<<dim3(Dd / 128, Nn / 128, Bb * Hh), blk>>>(x, W);
    k2_logits<<<dim3(Nn / 128, Nn / 128, Bb * Hh), blk>>>(x);
    k3_softmax_avg<<<dim3(Nn, Bb), blk>>>();
    k4_out<<<dim3(Dd / 128, Nn / 128, Bb), blk>>>(x, out);
}

// round 4
// speedup vs baseline: 1.0590x; 1.0590x over previous
#include <cuda_runtime.h>
#include <cuda_bf16.h>
#include <cstdint>

// Problem shapes (fixed by the dataset)
static constexpr int Bb = 8;     // batch
static constexpr int Nn = 1024;  // tokens
static constexpr int Dd = 512;   // feature dim
static constexpr int Hh = 4;     // heads
static constexpr float SCALE = 0.04419417382415922f; // 512^-0.5

// Scratch (allocation-free rule -> __device__ globals)
__device__ float g_Y[(size_t)Bb * Hh * Nn * Dd];   // 64 MB  : x @ W per (b,h)
__device__ float g_L[(size_t)Bb * Hh * Nn * Nn];   // 128 MB : logits per (b,h)
__device__ float g_P[(size_t)Bb * Nn * Nn];        // 32 MB  : head-averaged softmax

// ---------------------------------------------------------------------------
// Packed f32x2 helpers (FFMA2 — PTX-only, ptxas never auto-fuses)
// ---------------------------------------------------------------------------
__device__ __forceinline__ void fma2(unsigned long long& acc,
                                     unsigned long long a,
                                     unsigned long long b) {
    asm("fma.rn.f32x2 %0, %1, %2, %0;" : "+l"(acc) : "l"(a), "l"(b));
}
__device__ __forceinline__ unsigned long long bcast2(float v) {
    unsigned long long d;
    asm("mov.b64 %0, {%1, %1};" : "=l"(d) : "r"(__float_as_uint(v)));
    return d;
}

// ---------------------------------------------------------------------------
// fp32 FFMA2 SGEMM tile body: C = alpha * A * op(B)
//   A: [M,K] row-major (lda=K). TRANSB=false: B [K,N] row-major.
//   TRANSB=true: B [N,K] row-major.
//   BM=BN=128, BK=16, 256 threads, 8x8 per thread (packed 8x4 f32x2).
//   Register double-buffering of the gmem tile across the K loop.
// ---------------------------------------------------------------------------
template <bool TRANSB>
__device__ __forceinline__ void sgemm_body(
    const float* __restrict__ A, const float* __restrict__ B,
    float* __restrict__ C, int N, int K, int ldc, float alpha)
{
    __shared__ float As[16][128];
    __shared__ float Bs[16][128];

    const int tid   = threadIdx.x;
    const int mBase = blockIdx.y * 128;
    const int nBase = blockIdx.x * 128;
    const int ty    = tid >> 4;   // 0..15  (M direction)
    const int tx    = tid & 15;   // 0..15  (N direction)

    const int lda = K;
    const int ldb = TRANSB ? K : N;

    // A load pattern: row = tid>>1 (0..127), k half = (tid&1)*8
    const int arow = tid >> 1;
    const int akb  = (tid & 1) * 8;
    // B non-trans pattern: krow = tid>>4 (0..15), ncol = (tid&15)*8
    const int bkr  = tid >> 4;
    const int bnc  = (tid & 15) * 8;

    const float* Aptr = A + (size_t)(mBase + arow) * lda + akb;
    const float* Bptr = TRANSB
        ? B + (size_t)(nBase + arow) * ldb + akb
        : B + (size_t)bkr * ldb + nBase + bnc;

    unsigned long long acc[8][4] = {};   // 8 M x 4 f32x2 (8 N)

    float4 aR0, aR1, bR0, bR1;

    // prologue: load chunk 0
    aR0 = *(const float4*)(Aptr);
    aR1 = *(const float4*)(Aptr + 4);
    if (TRANSB) {
        bR0 = *(const float4*)(Bptr);
        bR1 = *(const float4*)(Bptr + 4);
    } else {
        bR0 = *(const float4*)(Bptr);
        bR1 = *(const float4*)(Bptr + 4);
    }

    const int nChunks = K >> 4;
    for (int ch = 0; ch < nChunks; ch++) {
        // store staged regs -> smem
        As[akb + 0][arow] = aR0.x; As[akb + 1][arow] = aR0.y;
        As[akb + 2][arow] = aR0.z; As[akb + 3][arow] = aR0.w;
        As[akb + 4][arow] = aR1.x; As[akb + 5][arow] = aR1.y;
        As[akb + 6][arow] = aR1.z; As[akb + 7][arow] = aR1.w;
        if (TRANSB) {
            Bs[akb + 0][arow] = bR0.x; Bs[akb + 1][arow] = bR0.y;
            Bs[akb + 2][arow] = bR0.z; Bs[akb + 3][arow] = bR0.w;
            Bs[akb + 4][arow] = bR1.x; Bs[akb + 5][arow] = bR1.y;
            Bs[akb + 6][arow] = bR1.z; Bs[akb + 7][arow] = bR1.w;
        } else {
            *(float4*)&Bs[bkr][bnc]     = bR0;
            *(float4*)&Bs[bkr][bnc + 4] = bR1;
        }
        __syncthreads();

        // prefetch next chunk into regs (overlaps with compute below)
        if (ch + 1 < nChunks) {
            const float* An = Aptr + (ch + 1) * 16;
            aR0 = *(const float4*)(An);
            aR1 = *(const float4*)(An + 4);
            if (TRANSB) {
                const float* Bn = Bptr + (ch + 1) * 16;
                bR0 = *(const float4*)(Bn);
                bR1 = *(const float4*)(Bn + 4);
            } else {
                const float* Bn = Bptr + (size_t)(ch + 1) * 16 * ldb;
                bR0 = *(const float4*)(Bn);
                bR1 = *(const float4*)(Bn + 4);
            }
        }

        // compute 16 k-steps
#pragma unroll
        for (int k = 0; k < 16; k++) {
            float4 b0 = *(const float4*)&Bs[k][tx * 8];
            float4 b1 = *(const float4*)&Bs[k][tx * 8 + 4];
            float4 a0 = *(const float4*)&As[k][ty * 8];
            float4 a1 = *(const float4*)&As[k][ty * 8 + 4];
            unsigned long long bp[4];
            bp[0] = *(unsigned long long*)&b0.x;
            bp[1] = *(unsigned long long*)&b0.z;
            bp[2] = *(unsigned long long*)&b1.x;
            bp[3] = *(unsigned long long*)&b1.z;
            unsigned long long ap[8];
            ap[0] = bcast2(a0.x); ap[1] = bcast2(a0.y);
            ap[2] = bcast2(a0.z); ap[3] = bcast2(a0.w);
            ap[4] = bcast2(a1.x); ap[5] = bcast2(a1.y);
            ap[6] = bcast2(a1.z); ap[7] = bcast2(a1.w);
#pragma unroll
            for (int i = 0; i < 8; i++)
#pragma unroll
                for (int j = 0; j < 4; j++)
                    fma2(acc[i][j], ap[i], bp[j]);
        }
        __syncthreads();
    }

    // epilogue
#pragma unroll
    for (int i = 0; i < 8; i++) {
        float* crow = C + (size_t)(mBase + ty * 8 + i) * ldc + nBase + tx * 8;
        float4 o0, o1;
        float2 v;
        v = *(float2*)&acc[i][0]; o0.x = alpha * v.x; o0.y = alpha * v.y;
        v = *(float2*)&acc[i][1]; o0.z = alpha * v.x; o0.w = alpha * v.y;
        v = *(float2*)&acc[i][2]; o1.x = alpha * v.x; o1.y = alpha * v.y;
        v = *(float2*)&acc[i][3]; o1.z = alpha * v.x; o1.w = alpha * v.y;
        *(float4*)(crow)     = o0;
        *(float4*)(crow + 4) = o1;
    }
}

// ---------------------------------------------------------------------------
// Kernel 1: Y[b,h] = x_b @ W_h      (B = W[h], [K=512,N=512] row-major)
// ---------------------------------------------------------------------------
__global__ void __launch_bounds__(256, 2) k1_xw(const float* __restrict__ x,
                                                const float* __restrict__ W)
{
    const int batch = blockIdx.z;        // b*4 + h
    const int b = batch >> 2, h = batch & 3;
    sgemm_body<false>(x + (size_t)b * Nn * Dd,
                      W + (size_t)h * Dd * Dd,
                      g_Y + (size_t)batch * Nn * Dd,
                      Dd, Dd, Dd, 1.0f);
}

// ---------------------------------------------------------------------------
// Kernel 2: L[b,h] = (Y[b,h] @ x_b^T) * scale    (B = x[b], [N=1024,K=512])
// ---------------------------------------------------------------------------
__global__ void __launch_bounds__(256, 2) k2_logits(const float* __restrict__ x)
{
    const int batch = blockIdx.z;
    const int b = batch >> 2;
    sgemm_body<true>(g_Y + (size_t)batch * Nn * Dd,
                     x + (size_t)b * Nn * Dd,
                     g_L + (size_t)batch * Nn * Nn,
                     Nn, Dd, Nn, SCALE);
}

// ---------------------------------------------------------------------------
// Kernel 3: Pavg[b,n,:] = (1/H) * sum_h softmax(L[b,h,n,:])   grid(1024, 8)
// Pure-FMA exp (MUFU.EX2 at rt_SMSP=8 would cost ~1ms for 134M exps).
// ---------------------------------------------------------------------------
__device__ __forceinline__ float fexp(float xv)
{
    float t  = fmaxf(xv * 1.44269504088896341f, -125.0f);
    float fi = floorf(t);
    float f  = t - fi;
    const float c1 = 0.69314718055994531f, c2 = 0.24022650695910072f,
                c3 = 0.05550410866482158f, c4 = 0.00961812910762848f,
                c5 = 0.00133335581464284f, c6 = 0.00015403530393382f;
    float p = fmaf(c6, f, c5);
    p = fmaf(p, f, c4);
    p = fmaf(p, f, c3);
    p = fmaf(p, f, c2);
    p = fmaf(p, f, c1);
    p = fmaf(p, f, 1.0f);
    int i = (int)fi;
    return p * __int_as_float((i + 127) << 23);
}

template <bool IS_MAX>
__device__ __forceinline__ float breduce(float v, float* red)
{
    const int lane = threadIdx.x & 31, warp = threadIdx.x >> 5;
#pragma unroll
    for (int o = 16; o; o >>= 1) {
        float t = __shfl_xor_sync(0xffffffffu, v, o);
        v = IS_MAX ? fmaxf(v, t) : (v + t);
    }
    if (lane == 0) red[warp] = v;
    __syncthreads();
    if (warp == 0) {
        float t2 = red[lane & 7];
#pragma unroll
        for (int o = 4; o; o >>= 1) {
            float t = __shfl_xor_sync(0xffffffffu, t2, o);
            t2 = IS_MAX ? fmaxf(t2, t) : (t2 + t);
        }
        if (lane == 0) red[0] = t2;
    }
    __syncthreads();
    float r = red[0];
    __syncthreads();
    return r;
}

__global__ void __launch_bounds__(256) k3_softmax_avg()
{
    __shared__ float red[8];
    const int n = blockIdx.x;
    const int b = blockIdx.y;
    const int tid = threadIdx.x;

    float acc0 = 0.f, acc1 = 0.f, acc2 = 0.f, acc3 = 0.f;
#pragma unroll
    for (int h = 0; h < Hh; h++) {
        const float* row = g_L + (((size_t)(b * Hh + h)) * Nn + n) * Nn;
        float4 v = *(const float4*)(row + tid * 4);
        float m = fmaxf(fmaxf(v.x, v.y), fmaxf(v.z, v.w));
        m = breduce<true>(m, red);
        float e0 = fexp(v.x - m), e1 = fexp(v.y - m);
        float e2 = fexp(v.z - m), e3 = fexp(v.w - m);
        float s = breduce<false>(e0 + e1 + e2 + e3, red);
        float inv = 0.25f / s;               // fold 1/H into the softmax
        acc0 = fmaf(e0, inv, acc0);
        acc1 = fmaf(e1, inv, acc1);
        acc2 = fmaf(e2, inv, acc2);
        acc3 = fmaf(e3, inv, acc3);
    }
    float4 o = make_float4(acc0, acc1, acc2, acc3);
    *(float4*)(g_P + ((size_t)(b * Nn + n)) * Nn + tid * 4) = o;
}

// ---------------------------------------------------------------------------
// Kernel 4: out[b] = Pavg[b] @ x_b   (B = x[b], [K=1024,N=512] row-major)
// ---------------------------------------------------------------------------
__global__ void __launch_bounds__(256, 2) k4_out(const float* __restrict__ x,
                                                 float* __restrict__ out)
{
    const int b = blockIdx.z;
    sgemm_body<false>(g_P + (size_t)b * Nn * Nn,
                      x + (size_t)b * Nn * Dd,
                      out + (size_t)b * Nn * Dd,
                      Dd, Nn, Dd, 1.0f);
}

// ---------------------------------------------------------------------------
extern "C" void kernel_launch(void* const* d_in, const int* in_sizes, int n_in,
                              void* d_out, int out_size)
{
    const float* x = (const float*)d_in[0];   // [8,1024,512]
    const float* W = (const float*)d_in[1];   // [4,512,512]
    float* out = (float*)d_out;               // [8,1024,512]

    dim3 blk(256);
    k1_xw<<<dim3(Dd / 128, Nn / 128, Bb * Hh), blk>>>(x, W);
    k2_logits<<<dim3(Nn / 128, Nn / 128, Bb * Hh), blk>>>(x);
    k3_softmax_avg<<<dim3(Nn, Bb), blk>>>();
    k4_out<<<dim3(Dd / 128, Nn / 128, Bb), blk>>>(x, out);
}

// round 5
// speedup vs baseline: 1.2625x; 1.1921x over previous
#include <cuda_runtime.h>
#include <cuda_bf16.h>
#include <cstdint>

// Problem shapes (fixed by the dataset)
static constexpr int Bb = 8;     // batch
static constexpr int Nn = 1024;  // tokens
static constexpr int Dd = 512;   // feature dim
static constexpr int Hh = 4;     // heads
static constexpr float SCALE = 0.04419417382415922f; // 512^-0.5

// Scratch (allocation-free rule -> __device__ globals)
__device__ float g_Y[(size_t)Bb * Hh * Nn * Dd];   // 64 MB
__device__ float g_L[(size_t)Bb * Hh * Nn * Nn];   // 128 MB
__device__ float g_P[(size_t)Bb * Nn * Nn];        // 32 MB

// ---------------------------------------------------------------------------
// m16n8k8 tf32 mma (base PTX ISA, sm_80+; runs on sm_103 tensor pipe)
// ---------------------------------------------------------------------------
__device__ __forceinline__ void mma_tf32(float* d, const float* a, const float* b)
{
    asm volatile(
        "mma.sync.aligned.m16n8k8.row.col.f32.tf32.tf32.f32 "
        "{%0,%1,%2,%3}, {%4,%5,%6,%7}, {%8,%9}, {%0,%1,%2,%3};"
        : "+f"(d[0]), "+f"(d[1]), "+f"(d[2]), "+f"(d[3])
        : "r"(__float_as_uint(a[0])), "r"(__float_as_uint(a[1])),
          "r"(__float_as_uint(a[2])), "r"(__float_as_uint(a[3])),
          "r"(__float_as_uint(b[0])), "r"(__float_as_uint(b[1])));
}

__device__ __forceinline__ float tf32_hi(float v)
{
    uint32_t r;
    asm("cvt.rna.tf32.f32 %0, %1;" : "=r"(r) : "f"(v));
    return __uint_as_float(r);
}

// ---------------------------------------------------------------------------
// 3xTF32 split GEMM body: C = alpha * A * op(B)
//   A [M,K] row-major. TRANSB=false: B [K,N] row-major. TRANSB=true: B [N,K].
//   BM=BN=128, BK=16. 256 threads = 8 warps (2 M x 4 N), warp tile 64x32.
//   smem layout [k][m]/[k][n] with stride 136 (conflict-free frag loads).
// ---------------------------------------------------------------------------
static constexpr int LDS = 136;

template <bool TRANSB>
__device__ __forceinline__ void sgemm_mma(
    const float* __restrict__ A, const float* __restrict__ B,
    float* __restrict__ C, int lda, int ldb, int ldc, int K, float alpha)
{
    __shared__ float sAh[16][LDS];
    __shared__ float sAl[16][LDS];
    __shared__ float sBh[16][LDS];
    __shared__ float sBl[16][LDS];

    const int tid  = threadIdx.x;
    const int lane = tid & 31;
    const int warp = tid >> 5;
    const int mBase = blockIdx.y * 128;
    const int nBase = blockIdx.x * 128;
    const int mw = (warp & 1) * 64;        // warp M offset
    const int nw = (warp >> 1) * 32;       // warp N offset
    const int ar = lane >> 2;              // 0..7
    const int ac = lane & 3;               // 0..3

    // gmem load patterns
    const int arow = tid >> 1;             // 0..127
    const int akh  = (tid & 1) * 8;        // 0 or 8
    const int bkr  = tid >> 4;             // 0..15 (DIRECT)
    const int bnc  = (tid & 15) * 8;       // 0..120 (DIRECT)

    const float* Aptr = A + (size_t)(mBase + arow) * lda + akh;
    const float* Bptr = TRANSB
        ? B + (size_t)(nBase + arow) * ldb + akh
        : B + (size_t)bkr * ldb + nBase + bnc;

    float acc[4][4][4] = {};               // [mi][nj][reg]

    float4 aR0, aR1, bR0, bR1;
    aR0 = *(const float4*)(Aptr);
    aR1 = *(const float4*)(Aptr + 4);
    bR0 = *(const float4*)(Bptr);
    bR1 = *(const float4*)(Bptr + 4);

    const int nChunks = K >> 4;
    for (int ch = 0; ch < nChunks; ch++) {
        // ---- split + store staged regs to smem ----
        {
            const float av[8] = { aR0.x, aR0.y, aR0.z, aR0.w,
                                  aR1.x, aR1.y, aR1.z, aR1.w };
#pragma unroll
            for (int i = 0; i < 8; i++) {
                float h = tf32_hi(av[i]);
                sAh[akh + i][arow] = h;
                sAl[akh + i][arow] = av[i] - h;
            }
            const float bv[8] = { bR0.x, bR0.y, bR0.z, bR0.w,
                                  bR1.x, bR1.y, bR1.z, bR1.w };
            if (TRANSB) {
#pragma unroll
                for (int i = 0; i < 8; i++) {
                    float h = tf32_hi(bv[i]);
                    sBh[akh + i][arow] = h;
                    sBl[akh + i][arow] = bv[i] - h;
                }
            } else {
#pragma unroll
                for (int i = 0; i < 8; i++) {
                    float h = tf32_hi(bv[i]);
                    sBh[bkr][bnc + i] = h;
                    sBl[bkr][bnc + i] = bv[i] - h;
                }
            }
        }
        __syncthreads();

        // ---- prefetch next chunk into regs ----
        if (ch + 1 < nChunks) {
            const float* An = Aptr + (ch + 1) * 16;
            aR0 = *(const float4*)(An);
            aR1 = *(const float4*)(An + 4);
            if (TRANSB) {
                const float* Bn = Bptr + (ch + 1) * 16;
                bR0 = *(const float4*)(Bn);
                bR1 = *(const float4*)(Bn + 4);
            } else {
                const float* Bn = Bptr + (size_t)(ch + 1) * 16 * ldb;
                bR0 = *(const float4*)(Bn);
                bR1 = *(const float4*)(Bn + 4);
            }
        }

        // ---- compute: 2 k8 substeps, 3 split passes each ----
#pragma unroll
        for (int ks = 0; ks < 16; ks += 8) {
            float ah[4][4], bhf[4][2];
#pragma unroll
            for (int mi = 0; mi < 4; mi++) {
                int m = mw + mi * 16 + ar;
                ah[mi][0] = sAh[ks + ac][m];
                ah[mi][1] = sAh[ks + ac][m + 8];
                ah[mi][2] = sAh[ks + ac + 4][m];
                ah[mi][3] = sAh[ks + ac + 4][m + 8];
            }
#pragma unroll
            for (int nj = 0; nj < 4; nj++) {
                int n = nw + nj * 8 + ar;
                bhf[nj][0] = sBh[ks + ac][n];
                bhf[nj][1] = sBh[ks + ac + 4][n];
            }
            // pass 1: hi * hi
#pragma unroll
            for (int mi = 0; mi < 4; mi++)
#pragma unroll
                for (int nj = 0; nj < 4; nj++)
                    mma_tf32(acc[mi][nj], ah[mi], bhf[nj]);

            // pass 2: hi * lo
            float blf[4][2];
#pragma unroll
            for (int nj = 0; nj < 4; nj++) {
                int n = nw + nj * 8 + ar;
                blf[nj][0] = sBl[ks + ac][n];
                blf[nj][1] = sBl[ks + ac + 4][n];
            }
#pragma unroll
            for (int mi = 0; mi < 4; mi++)
#pragma unroll
                for (int nj = 0; nj < 4; nj++)
                    mma_tf32(acc[mi][nj], ah[mi], blf[nj]);

            // pass 3: lo * hi
            float alf[4][4];
#pragma unroll
            for (int mi = 0; mi < 4; mi++) {
                int m = mw + mi * 16 + ar;
                alf[mi][0] = sAl[ks + ac][m];
                alf[mi][1] = sAl[ks + ac][m + 8];
                alf[mi][2] = sAl[ks + ac + 4][m];
                alf[mi][3] = sAl[ks + ac + 4][m + 8];
            }
#pragma unroll
            for (int mi = 0; mi < 4; mi++)
#pragma unroll
                for (int nj = 0; nj < 4; nj++)
                    mma_tf32(acc[mi][nj], alf[mi], bhf[nj]);
        }
        __syncthreads();
    }

    // ---- epilogue ----
#pragma unroll
    for (int mi = 0; mi < 4; mi++) {
#pragma unroll
        for (int nj = 0; nj < 4; nj++) {
            int row = mBase + mw + mi * 16 + ar;
            int col = nBase + nw + nj * 8 + ac * 2;
            float2 v0, v1;
            v0.x = alpha * acc[mi][nj][0];
            v0.y = alpha * acc[mi][nj][1];
            v1.x = alpha * acc[mi][nj][2];
            v1.y = alpha * acc[mi][nj][3];
            *(float2*)(C + (size_t)row * ldc + col)       = v0;
            *(float2*)(C + (size_t)(row + 8) * ldc + col) = v1;
        }
    }
}

// ---------------------------------------------------------------------------
// Kernel 1: Y[b,h] = x_b @ W_h    (B = W[h] [K,N] row-major, DIRECT)
// ---------------------------------------------------------------------------
__global__ void __launch_bounds__(256, 2) k1_xw(const float* __restrict__ x,
                                                const float* __restrict__ W)
{
    const int batch = blockIdx.z;
    const int b = batch >> 2, h = batch & 3;
    sgemm_mma<false>(x + (size_t)b * Nn * Dd,
                     W + (size_t)h * Dd * Dd,
                     g_Y + (size_t)batch * Nn * Dd,
                     Dd, Dd, Dd, Dd, 1.0f);
}

// ---------------------------------------------------------------------------
// Kernel 2: L[b,h] = (Y[b,h] @ x_b^T) * scale   (B = x[b] [N,K], TRANS)
// ---------------------------------------------------------------------------
__global__ void __launch_bounds__(256, 2) k2_logits(const float* __restrict__ x)
{
    const int batch = blockIdx.z;
    const int b = batch >> 2;
    sgemm_mma<true>(g_Y + (size_t)batch * Nn * Dd,
                    x + (size_t)b * Nn * Dd,
                    g_L + (size_t)batch * Nn * Nn,
                    Dd, Dd, Nn, Dd, SCALE);
}

// ---------------------------------------------------------------------------
// Kernel 3: Pavg[b,n,:] = (1/H) * sum_h softmax(L[b,h,n,:])   grid(1024, 8)
// ---------------------------------------------------------------------------
__device__ __forceinline__ float fexp(float xv)
{
    float t  = fmaxf(xv * 1.44269504088896341f, -125.0f);
    float fi = floorf(t);
    float f  = t - fi;
    const float c1 = 0.69314718055994531f, c2 = 0.24022650695910072f,
                c3 = 0.05550410866482158f, c4 = 0.00961812910762848f,
                c5 = 0.00133335581464284f, c6 = 0.00015403530393382f;
    float p = fmaf(c6, f, c5);
    p = fmaf(p, f, c4);
    p = fmaf(p, f, c3);
    p = fmaf(p, f, c2);
    p = fmaf(p, f, c1);
    p = fmaf(p, f, 1.0f);
    int i = (int)fi;
    return p * __int_as_float((i + 127) << 23);
}

template <bool IS_MAX>
__device__ __forceinline__ float breduce(float v, float* red)
{
    const int lane = threadIdx.x & 31, warp = threadIdx.x >> 5;
#pragma unroll
    for (int o = 16; o; o >>= 1) {
        float t = __shfl_xor_sync(0xffffffffu, v, o);
        v = IS_MAX ? fmaxf(v, t) : (v + t);
    }
    if (lane == 0) red[warp] = v;
    __syncthreads();
    if (warp == 0) {
        float t2 = red[lane & 7];
#pragma unroll
        for (int o = 4; o; o >>= 1) {
            float t = __shfl_xor_sync(0xffffffffu, t2, o);
            t2 = IS_MAX ? fmaxf(t2, t) : (t2 + t);
        }
        if (lane == 0) red[0] = t2;
    }
    __syncthreads();
    float r = red[0];
    __syncthreads();
    return r;
}

__global__ void __launch_bounds__(256) k3_softmax_avg()
{
    __shared__ float red[8];
    const int n = blockIdx.x;
    const int b = blockIdx.y;
    const int tid = threadIdx.x;

    float acc0 = 0.f, acc1 = 0.f, acc2 = 0.f, acc3 = 0.f;
#pragma unroll
    for (int h = 0; h < Hh; h++) {
        const float* row = g_L + (((size_t)(b * Hh + h)) * Nn + n) * Nn;
        float4 v = *(const float4*)(row + tid * 4);
        float m = fmaxf(fmaxf(v.x, v.y), fmaxf(v.z, v.w));
        m = breduce<true>(m, red);
        float e0 = fexp(v.x - m), e1 = fexp(v.y - m);
        float e2 = fexp(v.z - m), e3 = fexp(v.w - m);
        float s = breduce<false>(e0 + e1 + e2 + e3, red);
        float inv = 0.25f / s;
        acc0 = fmaf(e0, inv, acc0);
        acc1 = fmaf(e1, inv, acc1);
        acc2 = fmaf(e2, inv, acc2);
        acc3 = fmaf(e3, inv, acc3);
    }
    float4 o = make_float4(acc0, acc1, acc2, acc3);
    *(float4*)(g_P + ((size_t)(b * Nn + n)) * Nn + tid * 4) = o;
}

// ---------------------------------------------------------------------------
// Kernel 4: out[b] = Pavg[b] @ x_b   (B = x[b] [K,N] row-major, DIRECT)
// ---------------------------------------------------------------------------
__global__ void __launch_bounds__(256, 2) k4_out(const float* __restrict__ x,
                                                 float* __restrict__ out)
{
    const int b = blockIdx.z;
    sgemm_mma<false>(g_P + (size_t)b * Nn * Nn,
                     x + (size_t)b * Nn * Dd,
                     out + (size_t)b * Nn * Dd,
                     Nn, Dd, Dd, Nn, 1.0f);
}

// ---------------------------------------------------------------------------
extern "C" void kernel_launch(void* const* d_in, const int* in_sizes, int n_in,
                              void* d_out, int out_size)
{
    const float* x = (const float*)d_in[0];   // [8,1024,512]
    const float* W = (const float*)d_in[1];   // [4,512,512]
    float* out = (float*)d_out;               // [8,1024,512]

    dim3 blk(256);
    k1_xw<<<dim3(Dd / 128, Nn / 128, Bb * Hh), blk>>>(x, W);
    k2_logits<<<dim3(Nn / 128, Nn / 128, Bb * Hh), blk>>>(x);
    k3_softmax_avg<<<dim3(Nn, Bb), blk>>>();
    k4_out<<<dim3(Dd / 128, Nn / 128, Bb), blk>>>(x, out);
}

// round 6
// speedup vs baseline: 1.5175x; 1.2020x over previous
#include <cuda_runtime.h>
#include <cuda_bf16.h>
#include <cstdint>

// Problem shapes (fixed by the dataset)
static constexpr int Bb = 8;     // batch
static constexpr int Nn = 1024;  // tokens
static constexpr int Dd = 512;   // feature dim
static constexpr int Hh = 4;     // heads
static constexpr float SCALE = 0.04419417382415922f; // 512^-0.5

// Scratch (allocation-free rule -> __device__ globals)
__device__ float g_Y[(size_t)Bb * Hh * Nn * Dd];   // 64 MB
__device__ float g_L[(size_t)Bb * Hh * Nn * Nn];   // 128 MB
__device__ float g_P[(size_t)Bb * Nn * Nn];        // 32 MB

// ---------------------------------------------------------------------------
// PTX helpers (all base-ISA, sm_80+)
// ---------------------------------------------------------------------------
__device__ __forceinline__ void mma_tf32(float* d, const float* a, const float* b)
{
    asm volatile(
        "mma.sync.aligned.m16n8k8.row.col.f32.tf32.tf32.f32 "
        "{%0,%1,%2,%3}, {%4,%5,%6,%7}, {%8,%9}, {%0,%1,%2,%3};"
        : "+f"(d[0]), "+f"(d[1]), "+f"(d[2]), "+f"(d[3])
        : "r"(__float_as_uint(a[0])), "r"(__float_as_uint(a[1])),
          "r"(__float_as_uint(a[2])), "r"(__float_as_uint(a[3])),
          "r"(__float_as_uint(b[0])), "r"(__float_as_uint(b[1])));
}

__device__ __forceinline__ float tf32_hi(float v)
{
    uint32_t r;
    asm("cvt.rna.tf32.f32 %0, %1;" : "=r"(r) : "f"(v));
    return __uint_as_float(r);
}

__device__ __forceinline__ uint32_t smem_u32(const void* p) {
    uint32_t a;
    asm("{ .reg .u64 t; cvta.to.shared.u64 t, %1; cvt.u32.u64 %0, t; }"
        : "=r"(a) : "l"(p));
    return a;
}

__device__ __forceinline__ void cp16(void* smem, const void* gmem) {
    asm volatile("cp.async.cg.shared.global [%0], [%1], 16;"
                 :: "r"(smem_u32(smem)), "l"(gmem));
}
__device__ __forceinline__ void cp_commit() {
    asm volatile("cp.async.commit_group;" ::: "memory");
}
__device__ __forceinline__ void cp_wait0() {
    asm volatile("cp.async.wait_group 0;" ::: "memory");
}

// ---------------------------------------------------------------------------
// 3xTF32 split GEMM: C = alpha * A * op(B)
//   A [M,K] row-major. TRANSB=false: B [K,N] row-major. TRANSB=true: B [N,K].
//   BM=BN=128, BK=16, 256 threads = 8 warps (2 M x 4 N), warp tile 64x32.
//   Raw fp32 tiles in smem (cp.async, double-buffered); hi/lo split happens
//   in registers at fragment-load time (halves LDS traffic vs split-at-STS).
//   A / trans-B smem: [row][16+4] (stride 20 -> conflict-free frag loads).
//   non-trans-B smem: [k][128+8]  (stride 136 -> conflict-free frag loads).
// ---------------------------------------------------------------------------
template <bool TRANSB>
__device__ __forceinline__ void sgemm_mma(
    const float* __restrict__ A, const float* __restrict__ B,
    float* __restrict__ C, int lda, int ldb, int ldc, int K, float alpha)
{
    constexpr int BSZ = TRANSB ? 128 * 20 : 16 * 136;
    __shared__ float sA[2][128 * 20];
    __shared__ float sB[2][BSZ];

    const int tid  = threadIdx.x;
    const int lane = tid & 31;
    const int warp = tid >> 5;
    const int mBase = blockIdx.y * 128;
    const int nBase = blockIdx.x * 128;
    const int mw = (warp & 1) * 64;
    const int nw = (warp >> 1) * 32;
    const int ar = lane >> 2;   // 0..7
    const int ac = lane & 3;    // 0..3

    const float* Abase = A + (size_t)mBase * lda;
    const float* Bbase = TRANSB ? B + (size_t)nBase * ldb : B + nBase;

    // async tile loaders (512 x 16B chunks each; 2 per thread)
    auto loadA = [&](int ch, int buf) {
#pragma unroll
        for (int i = 0; i < 2; i++) {
            int idx = tid + i * 256;
            int row = idx >> 2, c = (idx & 3) * 4;
            cp16(&sA[buf][row * 20 + c], Abase + (size_t)row * lda + ch * 16 + c);
        }
    };
    auto loadB = [&](int ch, int buf) {
        if (TRANSB) {
#pragma unroll
            for (int i = 0; i < 2; i++) {
                int idx = tid + i * 256;
                int row = idx >> 2, c = (idx & 3) * 4;
                cp16(&sB[buf][row * 20 + c], Bbase + (size_t)row * ldb + ch * 16 + c);
            }
        } else {
#pragma unroll
            for (int i = 0; i < 2; i++) {
                int idx = tid + i * 256;
                int kr = idx >> 5, c = (idx & 31) * 4;
                cp16(&sB[buf][kr * 136 + c],
                     Bbase + (size_t)(ch * 16 + kr) * ldb + c);
            }
        }
    };

    float acc[4][4][4] = {};   // [mi][nj][reg]

    loadA(0, 0); loadB(0, 0); cp_commit();

    const int nChunks = K >> 4;
    for (int ch = 0; ch < nChunks; ch++) {
        cp_wait0();
        __syncthreads();
        if (ch + 1 < nChunks) {
            loadA(ch + 1, (ch + 1) & 1);
            loadB(ch + 1, (ch + 1) & 1);
            cp_commit();
        }
        const float* pA = sA[ch & 1];
        const float* pB = sB[ch & 1];

#pragma unroll
        for (int ks = 0; ks < 16; ks += 8) {
            // B fragments: load raw, split in regs
            float bh[4][2], bl[4][2];
#pragma unroll
            for (int nj = 0; nj < 4; nj++) {
                int n = nw + nj * 8 + ar;
                float r0 = TRANSB ? pB[n * 20 + ks + ac]
                                  : pB[(ks + ac) * 136 + n];
                float r1 = TRANSB ? pB[n * 20 + ks + ac + 4]
                                  : pB[(ks + ac + 4) * 136 + n];
                bh[nj][0] = tf32_hi(r0); bl[nj][0] = r0 - bh[nj][0];
                bh[nj][1] = tf32_hi(r1); bl[nj][1] = r1 - bh[nj][1];
            }
            // A fragments: raw + hi (lo computed after passes 1-2)
            float araw[4][4], ah[4][4];
#pragma unroll
            for (int mi = 0; mi < 4; mi++) {
                int m = mw + mi * 16 + ar;
                araw[mi][0] = pA[m * 20 + ks + ac];
                araw[mi][1] = pA[(m + 8) * 20 + ks + ac];
                araw[mi][2] = pA[m * 20 + ks + ac + 4];
                araw[mi][3] = pA[(m + 8) * 20 + ks + ac + 4];
#pragma unroll
                for (int t = 0; t < 4; t++) ah[mi][t] = tf32_hi(araw[mi][t]);
            }
            // pass 1: hi * hi
#pragma unroll
            for (int mi = 0; mi < 4; mi++)
#pragma unroll
                for (int nj = 0; nj < 4; nj++)
                    mma_tf32(acc[mi][nj], ah[mi], bh[nj]);
            // pass 2: hi * lo
#pragma unroll
            for (int mi = 0; mi < 4; mi++)
#pragma unroll
                for (int nj = 0; nj < 4; nj++)
                    mma_tf32(acc[mi][nj], ah[mi], bl[nj]);
            // pass 3: lo * hi
            float al[4][4];
#pragma unroll
            for (int mi = 0; mi < 4; mi++)
#pragma unroll
                for (int t = 0; t < 4; t++)
                    al[mi][t] = araw[mi][t] - ah[mi][t];
#pragma unroll
            for (int mi = 0; mi < 4; mi++)
#pragma unroll
                for (int nj = 0; nj < 4; nj++)
                    mma_tf32(acc[mi][nj], al[mi], bh[nj]);
        }
        __syncthreads();
    }

    // ---- epilogue ----
#pragma unroll
    for (int mi = 0; mi < 4; mi++) {
#pragma unroll
        for (int nj = 0; nj < 4; nj++) {
            int row = mBase + mw + mi * 16 + ar;
            int col = nBase + nw + nj * 8 + ac * 2;
            float2 v0, v1;
            v0.x = alpha * acc[mi][nj][0];
            v0.y = alpha * acc[mi][nj][1];
            v1.x = alpha * acc[mi][nj][2];
            v1.y = alpha * acc[mi][nj][3];
            *(float2*)(C + (size_t)row * ldc + col)       = v0;
            *(float2*)(C + (size_t)(row + 8) * ldc + col) = v1;
        }
    }
}

// ---------------------------------------------------------------------------
// Kernel 1: Y[b,h] = x_b @ W_h    (B = W[h] [K,N] row-major, DIRECT)
// ---------------------------------------------------------------------------
__global__ void __launch_bounds__(256, 2) k1_xw(const float* __restrict__ x,
                                                const float* __restrict__ W)
{
    const int batch = blockIdx.z;
    const int b = batch >> 2, h = batch & 3;
    sgemm_mma<false>(x + (size_t)b * Nn * Dd,
                     W + (size_t)h * Dd * Dd,
                     g_Y + (size_t)batch * Nn * Dd,
                     Dd, Dd, Dd, Dd, 1.0f);
}

// ---------------------------------------------------------------------------
// Kernel 2: L[b,h] = (Y[b,h] @ x_b^T) * scale   (B = x[b] [N,K], TRANS)
// ---------------------------------------------------------------------------
__global__ void __launch_bounds__(256, 2) k2_logits(const float* __restrict__ x)
{
    const int batch = blockIdx.z;
    const int b = batch >> 2;
    sgemm_mma<true>(g_Y + (size_t)batch * Nn * Dd,
                    x + (size_t)b * Nn * Dd,
                    g_L + (size_t)batch * Nn * Nn,
                    Dd, Dd, Nn, Dd, SCALE);
}

// ---------------------------------------------------------------------------
// Kernel 3: Pavg[b,n,:] = (1/H) * sum_h softmax(L[b,h,n,:])   grid(1024, 8)
// Pure-FMA exp (MUFU.EX2 at rt_SMSP=8 would cost ~1ms for 134M exps).
// ---------------------------------------------------------------------------
__device__ __forceinline__ float fexp(float xv)
{
    float t  = fmaxf(xv * 1.44269504088896341f, -125.0f);
    float fi = floorf(t);
    float f  = t - fi;
    const float c1 = 0.69314718055994531f, c2 = 0.24022650695910072f,
                c3 = 0.05550410866482158f, c4 = 0.00961812910762848f,
                c5 = 0.00133335581464284f, c6 = 0.00015403530393382f;
    float p = fmaf(c6, f, c5);
    p = fmaf(p, f, c4);
    p = fmaf(p, f, c3);
    p = fmaf(p, f, c2);
    p = fmaf(p, f, c1);
    p = fmaf(p, f, 1.0f);
    int i = (int)fi;
    return p * __int_as_float((i + 127) << 23);
}

template <bool IS_MAX>
__device__ __forceinline__ float breduce(float v, float* red)
{
    const int lane = threadIdx.x & 31, warp = threadIdx.x >> 5;
#pragma unroll
    for (int o = 16; o; o >>= 1) {
        float t = __shfl_xor_sync(0xffffffffu, v, o);
        v = IS_MAX ? fmaxf(v, t) : (v + t);
    }
    if (lane == 0) red[warp] = v;
    __syncthreads();
    if (warp == 0) {
        float t2 = red[lane & 7];
#pragma unroll
        for (int o = 4; o; o >>= 1) {
            float t = __shfl_xor_sync(0xffffffffu, t2, o);
            t2 = IS_MAX ? fmaxf(t2, t) : (t2 + t);
        }
        if (lane == 0) red[0] = t2;
    }
    __syncthreads();
    float r = red[0];
    __syncthreads();
    return r;
}

__global__ void __launch_bounds__(256) k3_softmax_avg()
{
    __shared__ float red[8];
    const int n = blockIdx.x;
    const int b = blockIdx.y;
    const int tid = threadIdx.x;

    float acc0 = 0.f, acc1 = 0.f, acc2 = 0.f, acc3 = 0.f;
#pragma unroll
    for (int h = 0; h < Hh; h++) {
        const float* row = g_L + (((size_t)(b * Hh + h)) * Nn + n) * Nn;
        float4 v = *(const float4*)(row + tid * 4);
        float m = fmaxf(fmaxf(v.x, v.y), fmaxf(v.z, v.w));
        m = breduce<true>(m, red);
        float e0 = fexp(v.x - m), e1 = fexp(v.y - m);
        float e2 = fexp(v.z - m), e3 = fexp(v.w - m);
        float s = breduce<false>(e0 + e1 + e2 + e3, red);
        float inv = 0.25f / s;
        acc0 = fmaf(e0, inv, acc0);
        acc1 = fmaf(e1, inv, acc1);
        acc2 = fmaf(e2, inv, acc2);
        acc3 = fmaf(e3, inv, acc3);
    }
    float4 o = make_float4(acc0, acc1, acc2, acc3);
    *(float4*)(g_P + ((size_t)(b * Nn + n)) * Nn + tid * 4) = o;
}

// ---------------------------------------------------------------------------
// Kernel 4: out[b] = Pavg[b] @ x_b   (B = x[b] [K,N] row-major, DIRECT)
// ---------------------------------------------------------------------------
__global__ void __launch_bounds__(256, 2) k4_out(const float* __restrict__ x,
                                                 float* __restrict__ out)
{
    const int b = blockIdx.z;
    sgemm_mma<false>(g_P + (size_t)b * Nn * Nn,
                     x + (size_t)b * Nn * Dd,
                     out + (size_t)b * Nn * Dd,
                     Nn, Dd, Dd, Nn, 1.0f);
}

// ---------------------------------------------------------------------------
extern "C" void kernel_launch(void* const* d_in, const int* in_sizes, int n_in,
                              void* d_out, int out_size)
{
    const float* x = (const float*)d_in[0];   // [8,1024,512]
    const float* W = (const float*)d_in[1];   // [4,512,512]
    float* out = (float*)d_out;               // [8,1024,512]

    dim3 blk(256);
    k1_xw<<<dim3(Dd / 128, Nn / 128, Bb * Hh), blk>>>(x, W);
    k2_logits<<<dim3(Nn / 128, Nn / 128, Bb * Hh), blk>>>(x);
    k3_softmax_avg<<<dim3(Nn, Bb), blk>>>();
    k4_out<<<dim3(Dd / 128, Nn / 128, Bb), blk>>>(x, out);
}

// round 7
// speedup vs baseline: 2.0778x; 1.3692x over previous
#include <cuda_runtime.h>
#include <cuda_bf16.h>
#include <cstdint>

// Problem shapes (fixed by the dataset)
static constexpr int Bb = 8;     // batch
static constexpr int Nn = 1024;  // tokens
static constexpr int Dd = 512;   // feature dim
static constexpr int Hh = 4;     // heads
static constexpr float SCALE = 0.04419417382415922f; // 512^-0.5

typedef __nv_bfloat16 bf16;

// Scratch (allocation-free rule -> __device__ globals)
__device__ float g_L   [(size_t)Bb * Hh * Nn * Nn];  // 128 MB logits (fp32)
__device__ bf16  g_xb0 [(size_t)Bb * Nn * Dd];       // x split  [b][n][d]
__device__ bf16  g_xb1 [(size_t)Bb * Nn * Dd];
__device__ bf16  g_xtb0[(size_t)Bb * Dd * Nn];       // x^T split [b][d][n]
__device__ bf16  g_xtb1[(size_t)Bb * Dd * Nn];
__device__ bf16  g_Wtb0[(size_t)Hh * Dd * Dd];       // W^T split [h][n][k]
__device__ bf16  g_Wtb1[(size_t)Hh * Dd * Dd];
__device__ bf16  g_Yb0 [(size_t)Bb * Hh * Nn * Dd];  // Y split  [bh][n][d]
__device__ bf16  g_Yb1 [(size_t)Bb * Hh * Nn * Dd];
__device__ bf16  g_Pb0 [(size_t)Bb * Nn * Nn];       // Pavg split [b][n][m]
__device__ bf16  g_Pb1 [(size_t)Bb * Nn * Nn];

// ---------------------------------------------------------------------------
// PTX helpers (all base-ISA, sm_80+)
// ---------------------------------------------------------------------------
__device__ __forceinline__ void mma_bf16(float* d, const uint32_t* a, const uint32_t* b)
{
    asm volatile(
        "mma.sync.aligned.m16n8k16.row.col.f32.bf16.bf16.f32 "
        "{%0,%1,%2,%3}, {%4,%5,%6,%7}, {%8,%9}, {%0,%1,%2,%3};"
        : "+f"(d[0]), "+f"(d[1]), "+f"(d[2]), "+f"(d[3])
        : "r"(a[0]), "r"(a[1]), "r"(a[2]), "r"(a[3]), "r"(b[0]), "r"(b[1]));
}

__device__ __forceinline__ uint32_t smem_u32(const void* p) {
    uint32_t a;
    asm("{ .reg .u64 t; cvta.to.shared.u64 t, %1; cvt.u32.u64 %0, t; }"
        : "=r"(a) : "l"(p));
    return a;
}
__device__ __forceinline__ void cp16(void* smem, const void* gmem) {
    asm volatile("cp.async.cg.shared.global [%0], [%1], 16;"
                 :: "r"(smem_u32(smem)), "l"(gmem));
}
__device__ __forceinline__ void cp_commit() {
    asm volatile("cp.async.commit_group;" ::: "memory");
}
__device__ __forceinline__ void cp_wait0() {
    asm volatile("cp.async.wait_group 0;" ::: "memory");
}

// 2-way bf16 split: v = b0 + b1 + O(2^-17 |v|)
__device__ __forceinline__ void split2(float v, bf16& h, bf16& l)
{
    h = __float2bfloat16(v);
    l = __float2bfloat16(v - __bfloat162float(h));
}

// ---------------------------------------------------------------------------
// Split-2 bf16 GEMM: C = alpha * (A0+A1) * (B0+B1)^T  (b1*b1 term dropped)
//   A* [M,K] row-major bf16 splits, B* [N,K] row-major bf16 splits.
//   BM=BN=128, BK=16, 256 thr = 8 warps (2Mx4N), warp tile 64x32, m16n8k16.
//   smem [row][16+8pad] (stride 24) -> conflict-free u32 fragment loads.
//   EPI==0: fp32 C.  EPI==1: split-bf16 C (Cb0/Cb1).
// ---------------------------------------------------------------------------
static constexpr int PK = 24;    // padded K stride in elements

template <int EPI>
__device__ __forceinline__ void gemm_body(
    const bf16* __restrict__ Ab0, const bf16* __restrict__ Ab1,
    const bf16* __restrict__ Bb0, const bf16* __restrict__ Bb1,
    float* __restrict__ C, bf16* __restrict__ Cb0, bf16* __restrict__ Cb1,
    int lda, int ldb, int ldc, int K, float alpha)
{
    __shared__ bf16 sA0[2][128 * PK];
    __shared__ bf16 sA1[2][128 * PK];
    __shared__ bf16 sB0[2][128 * PK];
    __shared__ bf16 sB1[2][128 * PK];

    const int tid  = threadIdx.x;
    const int lane = tid & 31;
    const int warp = tid >> 5;
    const int mBase = blockIdx.y * 128;
    const int nBase = blockIdx.x * 128;
    const int mw  = (warp & 1) * 64;
    const int nw  = (warp >> 1) * 32;
    const int gid = lane >> 2;   // 0..7
    const int tig = lane & 3;    // 0..3

    const bf16* A0p = Ab0 + (size_t)mBase * lda;
    const bf16* A1p = Ab1 + (size_t)mBase * lda;
    const bf16* B0p = Bb0 + (size_t)nBase * ldb;
    const bf16* B1p = Bb1 + (size_t)nBase * ldb;

    // one 16B chunk per thread per tile (128 rows x 2 chunks = 256)
    const int lrow = tid >> 1;
    const int lchk = (tid & 1) * 8;

    auto loadTiles = [&](int ch, int buf) {
        size_t g = (size_t)lrow * lda + ch * 16 + lchk;
        cp16(&sA0[buf][lrow * PK + lchk], A0p + g);
        cp16(&sA1[buf][lrow * PK + lchk], A1p + g);
        size_t gb = (size_t)lrow * ldb + ch * 16 + lchk;
        cp16(&sB0[buf][lrow * PK + lchk], B0p + gb);
        cp16(&sB1[buf][lrow * PK + lchk], B1p + gb);
    };

    float acc[4][4][4] = {};   // [mi][nj][reg]

    loadTiles(0, 0); cp_commit();

    const int nChunks = K >> 4;
    for (int ch = 0; ch < nChunks; ch++) {
        cp_wait0();
        __syncthreads();
        if (ch + 1 < nChunks) {
            loadTiles(ch + 1, (ch + 1) & 1);
            cp_commit();
        }
        const int buf = ch & 1;
        const bf16* pA0 = sA0[buf];
        const bf16* pA1 = sA1[buf];
        const bf16* pB0 = sB0[buf];
        const bf16* pB1 = sB1[buf];

        // fragment offsets
        const int ko = tig * 2;

        uint32_t ah[4][4], bh[4][2];
#pragma unroll
        for (int nj = 0; nj < 4; nj++) {
            int n = nw + nj * 8 + gid;
            bh[nj][0] = *(const uint32_t*)&pB0[n * PK + ko];
            bh[nj][1] = *(const uint32_t*)&pB0[n * PK + ko + 8];
        }
#pragma unroll
        for (int mi = 0; mi < 4; mi++) {
            int m = mw + mi * 16 + gid;
            ah[mi][0] = *(const uint32_t*)&pA0[m * PK + ko];
            ah[mi][1] = *(const uint32_t*)&pA0[(m + 8) * PK + ko];
            ah[mi][2] = *(const uint32_t*)&pA0[m * PK + ko + 8];
            ah[mi][3] = *(const uint32_t*)&pA0[(m + 8) * PK + ko + 8];
        }
        // pass 1: A0 * B0
#pragma unroll
        for (int mi = 0; mi < 4; mi++)
#pragma unroll
            for (int nj = 0; nj < 4; nj++)
                mma_bf16(acc[mi][nj], ah[mi], bh[nj]);

        // pass 2: A0 * B1
        {
            uint32_t bl[4][2];
#pragma unroll
            for (int nj = 0; nj < 4; nj++) {
                int n = nw + nj * 8 + gid;
                bl[nj][0] = *(const uint32_t*)&pB1[n * PK + ko];
                bl[nj][1] = *(const uint32_t*)&pB1[n * PK + ko + 8];
            }
#pragma unroll
            for (int mi = 0; mi < 4; mi++)
#pragma unroll
                for (int nj = 0; nj < 4; nj++)
                    mma_bf16(acc[mi][nj], ah[mi], bl[nj]);
        }
        // pass 3: A1 * B0
        {
            uint32_t al[4][4];
#pragma unroll
            for (int mi = 0; mi < 4; mi++) {
                int m = mw + mi * 16 + gid;
                al[mi][0] = *(const uint32_t*)&pA1[m * PK + ko];
                al[mi][1] = *(const uint32_t*)&pA1[(m + 8) * PK + ko];
                al[mi][2] = *(const uint32_t*)&pA1[m * PK + ko + 8];
                al[mi][3] = *(const uint32_t*)&pA1[(m + 8) * PK + ko + 8];
            }
#pragma unroll
            for (int mi = 0; mi < 4; mi++)
#pragma unroll
                for (int nj = 0; nj < 4; nj++)
                    mma_bf16(acc[mi][nj], al[mi], bh[nj]);
        }
        __syncthreads();
    }

    // ---- epilogue ----
#pragma unroll
    for (int mi = 0; mi < 4; mi++) {
#pragma unroll
        for (int nj = 0; nj < 4; nj++) {
            int row = mBase + mw + mi * 16 + gid;
            int col = nBase + nw + nj * 8 + tig * 2;
#pragma unroll
            for (int half = 0; half < 2; half++) {
                int r = row + half * 8;
                float v0 = alpha * acc[mi][nj][half * 2 + 0];
                float v1 = alpha * acc[mi][nj][half * 2 + 1];
                if (EPI == 0) {
                    float2 o; o.x = v0; o.y = v1;
                    *(float2*)(C + (size_t)r * ldc + col) = o;
                } else {
                    bf16 h0, l0, h1, l1;
                    split2(v0, h0, l0);
                    split2(v1, h1, l1);
                    __nv_bfloat162 ph; ph.x = h0; ph.y = h1;
                    __nv_bfloat162 pl; pl.x = l0; pl.y = l1;
                    *(__nv_bfloat162*)(Cb0 + (size_t)r * ldc + col) = ph;
                    *(__nv_bfloat162*)(Cb1 + (size_t)r * ldc + col) = pl;
                }
            }
        }
    }
}

// ---------------------------------------------------------------------------
// GEMM kernels
// ---------------------------------------------------------------------------
// k1: Y[b,h] = x_b @ W_h   -> split-bf16 output
__global__ void __launch_bounds__(256, 2) k1_xw()
{
    const int z = blockIdx.z;          // b*4 + h
    const int b = z >> 2, h = z & 3;
    gemm_body<1>(g_xb0 + (size_t)b * Nn * Dd, g_xb1 + (size_t)b * Nn * Dd,
                 g_Wtb0 + (size_t)h * Dd * Dd, g_Wtb1 + (size_t)h * Dd * Dd,
                 nullptr,
                 g_Yb0 + (size_t)z * Nn * Dd, g_Yb1 + (size_t)z * Nn * Dd,
                 Dd, Dd, Dd, Dd, 1.0f);
}

// k2: L[b,h] = (Y @ x_b^T) * scale  -> fp32 output
__global__ void __launch_bounds__(256, 2) k2_logits()
{
    const int z = blockIdx.z;
    const int b = z >> 2;
    gemm_body<0>(g_Yb0 + (size_t)z * Nn * Dd, g_Yb1 + (size_t)z * Nn * Dd,
                 g_xb0 + (size_t)b * Nn * Dd, g_xb1 + (size_t)b * Nn * Dd,
                 g_L + (size_t)z * Nn * Nn, nullptr, nullptr,
                 Dd, Dd, Nn, Dd, SCALE);
}

// k4: out[b] = Pavg_b @ x_b  -> fp32 output
__global__ void __launch_bounds__(256, 2) k4_out(float* __restrict__ out)
{
    const int b = blockIdx.z;
    gemm_body<0>(g_Pb0 + (size_t)b * Nn * Nn, g_Pb1 + (size_t)b * Nn * Nn,
                 g_xtb0 + (size_t)b * Dd * Nn, g_xtb1 + (size_t)b * Dd * Nn,
                 out + (size_t)b * Nn * Dd, nullptr, nullptr,
                 Nn, Nn, Dd, Nn, 1.0f);
}

// ---------------------------------------------------------------------------
// Pre-split kernels
// ---------------------------------------------------------------------------
__global__ void __launch_bounds__(256) splitX(const float* __restrict__ x)
{
    size_t i = ((size_t)blockIdx.x * 256 + threadIdx.x) * 4;
    float4 v = *(const float4*)(x + i);
    bf16 h0, l0, h1, l1, h2, l2, h3, l3;
    split2(v.x, h0, l0); split2(v.y, h1, l1);
    split2(v.z, h2, l2); split2(v.w, h3, l3);
    __nv_bfloat162 a, b, c, d;
    a.x = h0; a.y = h1; b.x = h2; b.y = h3;
    c.x = l0; c.y = l1; d.x = l2; d.y = l3;
    *(__nv_bfloat162*)(g_xb0 + i)     = a;
    *(__nv_bfloat162*)(g_xb0 + i + 2) = b;
    *(__nv_bfloat162*)(g_xb1 + i)     = c;
    *(__nv_bfloat162*)(g_xb1 + i + 2) = d;
}

__global__ void __launch_bounds__(256) transXsplit(const float* __restrict__ x)
{
    __shared__ float t[32][33];
    const int b = blockIdx.z;
    const int d0 = blockIdx.x * 32, n0 = blockIdx.y * 32;
    const float* xb = x + (size_t)b * Nn * Dd;
    for (int i = threadIdx.y; i < 32; i += 8)
        t[i][threadIdx.x] = xb[(size_t)(n0 + i) * Dd + d0 + threadIdx.x];
    __syncthreads();
    for (int i = threadIdx.y; i < 32; i += 8) {
        float v = t[threadIdx.x][i];
        bf16 h, l; split2(v, h, l);
        size_t o = (size_t)b * Dd * Nn + (size_t)(d0 + i) * Nn + n0 + threadIdx.x;
        g_xtb0[o] = h; g_xtb1[o] = l;
    }
}

__global__ void __launch_bounds__(256) transWsplit(const float* __restrict__ W)
{
    __shared__ float t[32][33];
    const int h = blockIdx.z;
    const int k0 = blockIdx.x * 32, n0 = blockIdx.y * 32;
    const float* Wh = W + (size_t)h * Dd * Dd;
    for (int i = threadIdx.y; i < 32; i += 8)
        t[i][threadIdx.x] = Wh[(size_t)(k0 + i) * Dd + n0 + threadIdx.x];
    __syncthreads();
    for (int i = threadIdx.y; i < 32; i += 8) {
        float v = t[threadIdx.x][i];
        bf16 hh, ll; split2(v, hh, ll);
        size_t o = (size_t)h * Dd * Dd + (size_t)(n0 + i) * Dd + k0 + threadIdx.x;
        g_Wtb0[o] = hh; g_Wtb1[o] = ll;
    }
}

// ---------------------------------------------------------------------------
// Kernel 3: Pavg[b,n,:] = (1/H) * sum_h softmax(L[b,h,n,:]) -> split bf16
// Pure-FMA exp (MUFU.EX2 at rt_SMSP=8 would cost ~1ms for 134M exps).
// ---------------------------------------------------------------------------
__device__ __forceinline__ float fexp(float xv)
{
    float t  = fmaxf(xv * 1.44269504088896341f, -125.0f);
    float fi = floorf(t);
    float f  = t - fi;
    const float c1 = 0.69314718055994531f, c2 = 0.24022650695910072f,
                c3 = 0.05550410866482158f, c4 = 0.00961812910762848f,
                c5 = 0.00133335581464284f, c6 = 0.00015403530393382f;
    float p = fmaf(c6, f, c5);
    p = fmaf(p, f, c4);
    p = fmaf(p, f, c3);
    p = fmaf(p, f, c2);
    p = fmaf(p, f, c1);
    p = fmaf(p, f, 1.0f);
    int i = (int)fi;
    return p * __int_as_float((i + 127) << 23);
}

template <bool IS_MAX>
__device__ __forceinline__ float breduce(float v, float* red)
{
    const int lane = threadIdx.x & 31, warp = threadIdx.x >> 5;
#pragma unroll
    for (int o = 16; o; o >>= 1) {
        float t = __shfl_xor_sync(0xffffffffu, v, o);
        v = IS_MAX ? fmaxf(v, t) : (v + t);
    }
    if (lane == 0) red[warp] = v;
    __syncthreads();
    if (warp == 0) {
        float t2 = red[lane & 7];
#pragma unroll
        for (int o = 4; o; o >>= 1) {
            float t = __shfl_xor_sync(0xffffffffu, t2, o);
            t2 = IS_MAX ? fmaxf(t2, t) : (t2 + t);
        }
        if (lane == 0) red[0] = t2;
    }
    __syncthreads();
    float r = red[0];
    __syncthreads();
    return r;
}

__global__ void __launch_bounds__(256) k3_softmax_avg()
{
    __shared__ float red[8];
    const int n = blockIdx.x;
    const int b = blockIdx.y;
    const int tid = threadIdx.x;

    float acc0 = 0.f, acc1 = 0.f, acc2 = 0.f, acc3 = 0.f;
#pragma unroll
    for (int h = 0; h < Hh; h++) {
        const float* row = g_L + (((size_t)(b * Hh + h)) * Nn + n) * Nn;
        float4 v = *(const float4*)(row + tid * 4);
        float m = fmaxf(fmaxf(v.x, v.y), fmaxf(v.z, v.w));
        m = breduce<true>(m, red);
        float e0 = fexp(v.x - m), e1 = fexp(v.y - m);
        float e2 = fexp(v.z - m), e3 = fexp(v.w - m);
        float s = breduce<false>(e0 + e1 + e2 + e3, red);
        float inv = 0.25f / s;
        acc0 = fmaf(e0, inv, acc0);
        acc1 = fmaf(e1, inv, acc1);
        acc2 = fmaf(e2, inv, acc2);
        acc3 = fmaf(e3, inv, acc3);
    }
    size_t o = ((size_t)(b * Nn + n)) * Nn + tid * 4;
    bf16 h0, l0, h1, l1, h2, l2, h3, l3;
    split2(acc0, h0, l0); split2(acc1, h1, l1);
    split2(acc2, h2, l2); split2(acc3, h3, l3);
    __nv_bfloat162 ph0, ph1, pl0, pl1;
    ph0.x = h0; ph0.y = h1; ph1.x = h2; ph1.y = h3;
    pl0.x = l0; pl0.y = l1; pl1.x = l2; pl1.y = l3;
    *(__nv_bfloat162*)(g_Pb0 + o)     = ph0;
    *(__nv_bfloat162*)(g_Pb0 + o + 2) = ph1;
    *(__nv_bfloat162*)(g_Pb1 + o)     = pl0;
    *(__nv_bfloat162*)(g_Pb1 + o + 2) = pl1;
}

// ---------------------------------------------------------------------------
extern "C" void kernel_launch(void* const* d_in, const int* in_sizes, int n_in,
                              void* d_out, int out_size)
{
    const float* x = (const float*)d_in[0];   // [8,1024,512]
    const float* W = (const float*)d_in[1];   // [4,512,512]
    float* out = (float*)d_out;               // [8,1024,512]

    dim3 blk(256);
    splitX<<<(Bb * Nn * Dd) / 1024, blk>>>(x);
    transXsplit<<<dim3(Dd / 32, Nn / 32, Bb), dim3(32, 8)>>>(x);
    transWsplit<<<dim3(Dd / 32, Dd / 32, Hh), dim3(32, 8)>>>(W);

    k1_xw<<<dim3(Dd / 128, Nn / 128, Bb * Hh), blk>>>();
    k2_logits<<<dim3(Nn / 128, Nn / 128, Bb * Hh), blk>>>();
    k3_softmax_avg<<<dim3(Nn, Bb), blk>>>();
    k4_out<<<dim3(Dd / 128, Nn / 128, Bb), blk>>>(out);
}